// round 11
// baseline (speedup 1.0000x reference)
#include <cuda_runtime.h>
#include <cuda_fp16.h>
#include <cstdint>

// ============================================================================
// R11: R10 (128x128 fp16 mma tiles, K-stage 64) + softmax hidden behind the
// V-projection: QKV split into QKproj (z=0,1) and a fused kernel where
// Vproj tiles (tensor-bound, blockIdx<512, launched first) co-execute with
// softmax blocks (memory-bound). Math identical to R10 -> same rel_err.
// Order: convert -> QKproj -> QKgemm -> fused(Vproj+softmax) -> PV.
// ============================================================================

using fp16 = __half;

// ---------------- scratch ----------------------------------------------------
__device__ __align__(256) fp16 g_x[8192 * 1024];
__device__ __align__(256) fp16 g_W[3 * 1024 * 1024];
__device__ __align__(256) fp16 g_Q[8192 * 1024];
__device__ __align__(256) fp16 g_K[8192 * 1024];
__device__ __align__(256) fp16 g_Vt[4 * 1024 * 2048];        // transposed
__device__ __align__(256) float g_S[4 * 2048 * 2048];
__device__ __align__(256) fp16 g_P[4 * 2048 * 2048];

// ---------------- PTX helpers -------------------------------------------------
__device__ __forceinline__ uint32_t smem_u32(const void* p) {
    uint32_t a;
    asm("{ .reg .u64 t; cvta.to.shared.u64 t, %1; cvt.u32.u64 %0, t; }" : "=r"(a) : "l"(p));
    return a;
}
__device__ __forceinline__ void cp16(uint32_t dst, const void* src) {
    asm volatile("cp.async.cg.shared.global [%0], [%1], 16;" :: "r"(dst), "l"(src));
}
#define CP_COMMIT() asm volatile("cp.async.commit_group;" ::: "memory")

__device__ __forceinline__ void ldm4(uint32_t* r, uint32_t a) {
    asm volatile("ldmatrix.sync.aligned.m8n8.x4.shared.b16 {%0,%1,%2,%3}, [%4];"
                 : "=r"(r[0]), "=r"(r[1]), "=r"(r[2]), "=r"(r[3]) : "r"(a));
}
__device__ __forceinline__ void mma_f16(float* c, const uint32_t* a, uint32_t b0, uint32_t b1) {
    asm volatile(
        "mma.sync.aligned.m16n8k16.row.col.f32.f16.f16.f32 "
        "{%0,%1,%2,%3}, {%4,%5,%6,%7}, {%8,%9}, {%0,%1,%2,%3};"
        : "+f"(c[0]), "+f"(c[1]), "+f"(c[2]), "+f"(c[3])
        : "r"(a[0]), "r"(a[1]), "r"(a[2]), "r"(a[3]), "r"(b0), "r"(b1));
}

// ---------------- SMEM layout -------------------------------------------------
// Per stage: A, B — each 128 rows x 64 fp16 (128B data), row stride 144B.
// ldmatrix phase (8 rows): banks 36r ≡ 4r mod 32, distinct. Conflict-free.
#define ROWB     144
#define ARR_B    (128 * ROWB)          // 18432
#define STG_B    (2 * ARR_B)           // 36864
#define SM_TOTAL (2 * STG_B)           // 73728

// ---------------- GEMM body: 128x128 tile, 256 thr, warps 2(m) x 4(n) --------
// MODE 0: QKV (z: 0->Q, 1->K, 2->V transposed) -> fp16
// MODE 1: QK  (z=batch), g_S = acc/32 fp32
// MODE 2: PV  (z=batch), out = acc fp32
template <int MODE>
__device__ __forceinline__ void gemm_body(
    const fp16* __restrict__ A, int lda,
    const fp16* __restrict__ B, int ldb,
    int K, float* __restrict__ outp,
    int bx, int by, int z)
{
    extern __shared__ char sm[];
    const uint32_t smb = smem_u32(sm);
    const int tid = threadIdx.x, lane = tid & 31, wid = tid >> 5;
    const int wm = wid & 1, wn = wid >> 1;          // warp tile: 64x32
    const int row0 = by * 128, col0 = bx * 128;

    float acc[4][4][4];
    #pragma unroll
    for (int i = 0; i < 4; ++i)
        #pragma unroll
        for (int j = 0; j < 4; ++j)
            #pragma unroll
            for (int k = 0; k < 4; ++k) acc[i][j][k] = 0.f;

    const fp16* pa = A + (size_t)row0 * lda;
    const fp16* pb = B + (size_t)col0 * ldb;

    auto load_stage = [&](int sbuf, int k0) {
        const uint32_t b = smb + sbuf * STG_B;
        #pragma unroll
        for (int v = 0; v < 4; ++v) {
            const int idx = tid + v * 256;       // 0..1023
            const int row = idx >> 3;            // 0..127
            const int kc  = idx & 7;             // 16B unit
            const uint32_t so = row * ROWB + kc * 16;
            cp16(b + so,         pa + (size_t)row * lda + k0 + kc * 8);
            cp16(b + ARR_B + so, pb + (size_t)row * ldb + k0 + kc * 8);
        }
        CP_COMMIT();
    };

    const int ns = K >> 6;   // 64 K per stage
    load_stage(0, 0);

    const uint32_t a_off = (wm * 64 + (lane & 15)) * ROWB + (lane >> 4) * 16;
    const uint32_t b_off = ARR_B
                         + (wn * 32 + (lane & 7) + ((lane >> 4) << 3)) * ROWB
                         + ((lane >> 3) & 1) * 16;

    for (int s = 0; s < ns; ++s) {
        if (s + 1 < ns) {
            load_stage((s + 1) & 1, (s + 1) * 64);
            asm volatile("cp.async.wait_group 1;" ::: "memory");
        } else {
            asm volatile("cp.async.wait_group 0;" ::: "memory");
        }
        __syncthreads();

        const uint32_t sb = smb + (s & 1) * STG_B;
        #pragma unroll
        for (int ks = 0; ks < 4; ++ks) {         // 4 k16 slices per stage
            const uint32_t ab = sb + a_off + ks * 32;
            const uint32_t bb = sb + b_off + ks * 32;
            uint32_t af[4][4], bf[2][4];
            #pragma unroll
            for (int mt = 0; mt < 4; ++mt)
                ldm4(af[mt], ab + mt * 16 * ROWB);
            #pragma unroll
            for (int bt = 0; bt < 2; ++bt)
                ldm4(bf[bt], bb + bt * 16 * ROWB);
            #pragma unroll
            for (int mt = 0; mt < 4; ++mt)
                #pragma unroll
                for (int nt = 0; nt < 4; ++nt) {
                    const int bt = nt >> 1, h = (nt & 1) * 2;
                    mma_f16(acc[mt][nt], af[mt], bf[bt][h], bf[bt][h + 1]);
                }
        }
        __syncthreads();
    }

    // ---- epilogue ----
    const int gr0 = row0 + wm * 64 + (lane >> 2);
    const int gc0 = col0 + wn * 32 + (lane & 3) * 2;

    #pragma unroll
    for (int mt = 0; mt < 4; ++mt)
        #pragma unroll
        for (int nt = 0; nt < 4; ++nt) {
            const int gr = gr0 + mt * 16;
            const int gc = gc0 + nt * 8;
            const float* c = acc[mt][nt];
            if (MODE == 0) {
                if (z == 2) {            // V: fp16, transposed Vt[(b*1024+n)][t]
                    const int b = gr >> 11, t = gr & 2047;
                    const size_t o = ((size_t)(b * 1024 + gc)) * 2048 + t;
                    g_Vt[o]            = __float2half(c[0]);
                    g_Vt[o + 2048]     = __float2half(c[1]);
                    g_Vt[o + 8]        = __float2half(c[2]);
                    g_Vt[o + 2048 + 8] = __float2half(c[3]);
                } else {                 // Q or K: fp16 row-major
                    fp16* d = (z == 0) ? g_Q : g_K;
                    const size_t o = (size_t)gr * 1024 + gc;
                    *(__half2*)(d + o)            = __floats2half2_rn(c[0], c[1]);
                    *(__half2*)(d + o + 8 * 1024) = __floats2half2_rn(c[2], c[3]);
                }
            } else if (MODE == 1) {
                float* p = g_S + ((size_t)z << 22) + (size_t)gr * 2048 + gc;
                *(float2*)p              = make_float2(c[0] * 0.03125f, c[1] * 0.03125f);
                *(float2*)(p + 8 * 2048) = make_float2(c[2] * 0.03125f, c[3] * 0.03125f);
            } else {
                float* p = outp + ((size_t)z << 21) + (size_t)gr * 1024 + gc;
                *(float2*)p              = make_float2(c[0], c[1]);
                *(float2*)(p + 8 * 1024) = make_float2(c[2], c[3]);
            }
        }
}

// ---------------- softmax body (row = one of 8192) ----------------------------
__device__ __forceinline__ void softmax_body(int rowid)
{
    size_t ro = (size_t)rowid * 2048;
    const float* p = g_S + ro;
    const int t = threadIdx.x;
    __shared__ float red[8];

    float v[8];
    float m = -1e30f;
    #pragma unroll
    for (int i = 0; i < 8; ++i) {
        v[i] = p[t + i * 256];
        m = fmaxf(m, v[i]);
    }
    #pragma unroll
    for (int o = 16; o; o >>= 1) m = fmaxf(m, __shfl_xor_sync(0xffffffffu, m, o));
    if ((t & 31) == 0) red[t >> 5] = m;
    __syncthreads();
    m = red[0];
    #pragma unroll
    for (int i = 1; i < 8; ++i) m = fmaxf(m, red[i]);
    __syncthreads();

    float s = 0.f;
    #pragma unroll
    for (int i = 0; i < 8; ++i) {
        v[i] = __expf(v[i] - m);
        s += v[i];
    }
    #pragma unroll
    for (int o = 16; o; o >>= 1) s += __shfl_xor_sync(0xffffffffu, s, o);
    if ((t & 31) == 0) red[t >> 5] = s;
    __syncthreads();
    s = red[0];
    #pragma unroll
    for (int i = 1; i < 8; ++i) s += red[i];

    const float inv = 1.0f / s;
    #pragma unroll
    for (int i = 0; i < 8; ++i) {
        size_t o = ro + t + i * 256;
        g_P[o] = __float2half(v[i] * inv);
    }
}

// ---------------- kernels -----------------------------------------------------
__global__ void __launch_bounds__(256)
qkproj_kernel()   // Q and K projections only (z = 0,1)
{
    gemm_body<0>(g_x, 1024, g_W + (size_t)blockIdx.z * 1024 * 1024, 1024,
                 1024, nullptr, blockIdx.x, blockIdx.y, blockIdx.z);
}

__global__ void __launch_bounds__(256)
qk_kernel()
{
    const size_t bo = (size_t)blockIdx.z << 21;   // b*2048*1024
    gemm_body<1>(g_Q + bo, 1024, g_K + bo, 1024, 1024, nullptr,
                 blockIdx.x, blockIdx.y, blockIdx.z);
}

// Fused: blocks [0,512) = V-projection tiles (tensor-bound, launched first);
// blocks [512, 8704) = softmax rows (memory-bound, fill idle slots).
#define VP_TILES 512      // 8 x 64
__global__ void __launch_bounds__(256)
vproj_softmax_kernel()
{
    const int b = blockIdx.x;
    if (b < VP_TILES) {
        const int bx = b & 7, by = b >> 3;
        gemm_body<0>(g_x, 1024, g_W + (size_t)2 * 1024 * 1024, 1024,
                     1024, nullptr, bx, by, 2);
    } else {
        softmax_body(b - VP_TILES);
    }
}

__global__ void __launch_bounds__(256)
pv_kernel(float* __restrict__ out)
{
    const size_t ao = (size_t)blockIdx.z << 22;   // b*2048*2048
    const size_t bo = (size_t)blockIdx.z << 21;   // b*1024*2048
    gemm_body<2>(g_P + ao, 2048, g_Vt + bo, 2048, 2048, out,
                 blockIdx.x, blockIdx.y, blockIdx.z);
}

// One launch converting x (2M float4) then Wq/Wk/Wv (256K float4 each).
#define N4_X (8192 * 1024 / 4)
#define N4_W (1024 * 1024 / 4)
__global__ void __launch_bounds__(256)
convert_all_kernel(const float* __restrict__ x, const float* __restrict__ Wq,
                   const float* __restrict__ Wk, const float* __restrict__ Wv)
{
    const int i = blockIdx.x * blockDim.x + threadIdx.x;
    const float* src;
    fp16* dst;
    int k;
    if (i < N4_X) {
        src = x; dst = g_x; k = i;
    } else {
        int j = i - N4_X;
        int w = j / N4_W;
        k = j - w * N4_W;
        src = (w == 0) ? Wq : (w == 1) ? Wk : Wv;
        dst = g_W + (size_t)w * 1024 * 1024;
    }
    float4 v = *(const float4*)(src + (size_t)k * 4);
    __half2* d = (__half2*)(dst + (size_t)k * 4);
    d[0] = __floats2half2_rn(v.x, v.y);
    d[1] = __floats2half2_rn(v.z, v.w);
}

// ---------------- launch ------------------------------------------------------
extern "C" void kernel_launch(void* const* d_in, const int* in_sizes, int n_in,
                              void* d_out, int out_size)
{
    const float* x  = (const float*)d_in[0];
    const float* Wq = (const float*)d_in[1];
    const float* Wk = (const float*)d_in[2];
    const float* Wv = (const float*)d_in[3];
    float* out = (float*)d_out;

    cudaFuncSetAttribute(qkproj_kernel,        cudaFuncAttributeMaxDynamicSharedMemorySize, SM_TOTAL);
    cudaFuncSetAttribute(qk_kernel,            cudaFuncAttributeMaxDynamicSharedMemorySize, SM_TOTAL);
    cudaFuncSetAttribute(vproj_softmax_kernel, cudaFuncAttributeMaxDynamicSharedMemorySize, SM_TOTAL);
    cudaFuncSetAttribute(pv_kernel,            cudaFuncAttributeMaxDynamicSharedMemorySize, SM_TOTAL);

    {
        int n4 = N4_X + 3 * N4_W;
        convert_all_kernel<<<(n4 + 255) / 256, 256>>>(x, Wq, Wk, Wv);
    }

    dim3 g1(8, 64, 2);    // Q,K projections
    qkproj_kernel<<<g1, 256, SM_TOTAL>>>();

    dim3 g2(16, 16, 4);   // QK: 2048x2048 per batch
    qk_kernel<<<g2, 256, SM_TOTAL>>>();

    // V projection (512 tiles, first) + softmax (8192 rows) fused
    vproj_softmax_kernel<<<VP_TILES + 8192, 256, SM_TOTAL>>>();

    dim3 g3(8, 16, 4);    // PV: 2048x1024, K=2048
    pv_kernel<<<g3, 256, SM_TOTAL>>>(out);
}

// round 12
// speedup vs baseline: 1.0717x; 1.0717x over previous
#include <cuda_runtime.h>
#include <cuda_fp16.h>
#include <cstdint>

// ============================================================================
// R12: R10 math (128x128 fp16 mma tiles, K-stage 64, rel_err 5.856e-4) with
// QKVproj and QK fused into ONE launch of same-resource CTAs:
//   blocks [0,1024)    : Q/K projections (z = idx/512)
//   blocks [1024,1536) : V projection (transposed store)
//   blocks [1536,2560) : QK gemm tiles, spin-waiting on per-128-row-block
//                        counters (8 N-tiles each) for their Q and K blocks.
// Producers: stores -> __threadfence -> __syncthreads -> tid0 atomicAdd.
// Consumers: tid0 ld.acquire spin -> __syncthreads. Counters zeroed by the
// convert kernel (prior launch in-stream, so valid under graph replay).
// Launch order: convert(+zero) -> mega(QKV+QK) -> softmax -> PV.
// ============================================================================

using fp16 = __half;

// ---------------- scratch ----------------------------------------------------
__device__ __align__(256) fp16 g_x[8192 * 1024];
__device__ __align__(256) fp16 g_W[3 * 1024 * 1024];
__device__ __align__(256) fp16 g_Q[8192 * 1024];
__device__ __align__(256) fp16 g_K[8192 * 1024];
__device__ __align__(256) fp16 g_Vt[4 * 1024 * 2048];        // transposed
__device__ __align__(256) float g_S[4 * 2048 * 2048];
__device__ __align__(256) fp16 g_P[4 * 2048 * 2048];
__device__ int g_cnt[128];      // [0..63]: Q 128-row blocks, [64..127]: K blocks

// ---------------- PTX helpers -------------------------------------------------
__device__ __forceinline__ uint32_t smem_u32(const void* p) {
    uint32_t a;
    asm("{ .reg .u64 t; cvta.to.shared.u64 t, %1; cvt.u32.u64 %0, t; }" : "=r"(a) : "l"(p));
    return a;
}
__device__ __forceinline__ void cp16(uint32_t dst, const void* src) {
    asm volatile("cp.async.cg.shared.global [%0], [%1], 16;" :: "r"(dst), "l"(src));
}
#define CP_COMMIT() asm volatile("cp.async.commit_group;" ::: "memory")

__device__ __forceinline__ void ldm4(uint32_t* r, uint32_t a) {
    asm volatile("ldmatrix.sync.aligned.m8n8.x4.shared.b16 {%0,%1,%2,%3}, [%4];"
                 : "=r"(r[0]), "=r"(r[1]), "=r"(r[2]), "=r"(r[3]) : "r"(a));
}
__device__ __forceinline__ void mma_f16(float* c, const uint32_t* a, uint32_t b0, uint32_t b1) {
    asm volatile(
        "mma.sync.aligned.m16n8k16.row.col.f32.f16.f16.f32 "
        "{%0,%1,%2,%3}, {%4,%5,%6,%7}, {%8,%9}, {%0,%1,%2,%3};"
        : "+f"(c[0]), "+f"(c[1]), "+f"(c[2]), "+f"(c[3])
        : "r"(a[0]), "r"(a[1]), "r"(a[2]), "r"(a[3]), "r"(b0), "r"(b1));
}
__device__ __forceinline__ int ld_acq(const int* p) {
    int v;
    asm volatile("ld.acquire.gpu.global.b32 %0, [%1];" : "=r"(v) : "l"(p) : "memory");
    return v;
}

// ---------------- SMEM layout -------------------------------------------------
// Per stage: A, B — each 128 rows x 64 fp16 (128B data), row stride 144B.
// ldmatrix phase (8 rows): banks 36r ≡ 4r mod 32, distinct. Conflict-free.
#define ROWB     144
#define ARR_B    (128 * ROWB)          // 18432
#define STG_B    (2 * ARR_B)           // 36864
#define SM_TOTAL (2 * STG_B)           // 73728

// ---------------- GEMM body: 128x128 tile, 256 thr, warps 2(m) x 4(n) --------
// MODE 0: QKV (z: 0->Q, 1->K, 2->V transposed) -> fp16 (+ counter arrive z<2)
// MODE 1: QK  (z=batch), g_S = acc/32 fp32
// MODE 2: PV  (z=batch), out = acc fp32
template <int MODE>
__device__ __forceinline__ void gemm_body(
    const fp16* __restrict__ A, int lda,
    const fp16* __restrict__ B, int ldb,
    int K, float* __restrict__ outp,
    int bx, int by, int z)
{
    extern __shared__ char sm[];
    const uint32_t smb = smem_u32(sm);
    const int tid = threadIdx.x, lane = tid & 31, wid = tid >> 5;
    const int wm = wid & 1, wn = wid >> 1;          // warp tile: 64x32
    const int row0 = by * 128, col0 = bx * 128;

    float acc[4][4][4];
    #pragma unroll
    for (int i = 0; i < 4; ++i)
        #pragma unroll
        for (int j = 0; j < 4; ++j)
            #pragma unroll
            for (int k = 0; k < 4; ++k) acc[i][j][k] = 0.f;

    const fp16* pa = A + (size_t)row0 * lda;
    const fp16* pb = B + (size_t)col0 * ldb;

    auto load_stage = [&](int sbuf, int k0) {
        const uint32_t b = smb + sbuf * STG_B;
        #pragma unroll
        for (int v = 0; v < 4; ++v) {
            const int idx = tid + v * 256;       // 0..1023
            const int row = idx >> 3;            // 0..127
            const int kc  = idx & 7;             // 16B unit
            const uint32_t so = row * ROWB + kc * 16;
            cp16(b + so,         pa + (size_t)row * lda + k0 + kc * 8);
            cp16(b + ARR_B + so, pb + (size_t)row * ldb + k0 + kc * 8);
        }
        CP_COMMIT();
    };

    const int ns = K >> 6;   // 64 K per stage
    load_stage(0, 0);

    const uint32_t a_off = (wm * 64 + (lane & 15)) * ROWB + (lane >> 4) * 16;
    const uint32_t b_off = ARR_B
                         + (wn * 32 + (lane & 7) + ((lane >> 4) << 3)) * ROWB
                         + ((lane >> 3) & 1) * 16;

    for (int s = 0; s < ns; ++s) {
        if (s + 1 < ns) {
            load_stage((s + 1) & 1, (s + 1) * 64);
            asm volatile("cp.async.wait_group 1;" ::: "memory");
        } else {
            asm volatile("cp.async.wait_group 0;" ::: "memory");
        }
        __syncthreads();

        const uint32_t sb = smb + (s & 1) * STG_B;
        #pragma unroll
        for (int ks = 0; ks < 4; ++ks) {         // 4 k16 slices per stage
            const uint32_t ab = sb + a_off + ks * 32;
            const uint32_t bb = sb + b_off + ks * 32;
            uint32_t af[4][4], bf[2][4];
            #pragma unroll
            for (int mt = 0; mt < 4; ++mt)
                ldm4(af[mt], ab + mt * 16 * ROWB);
            #pragma unroll
            for (int bt = 0; bt < 2; ++bt)
                ldm4(bf[bt], bb + bt * 16 * ROWB);
            #pragma unroll
            for (int mt = 0; mt < 4; ++mt)
                #pragma unroll
                for (int nt = 0; nt < 4; ++nt) {
                    const int bt = nt >> 1, h = (nt & 1) * 2;
                    mma_f16(acc[mt][nt], af[mt], bf[bt][h], bf[bt][h + 1]);
                }
        }
        __syncthreads();
    }

    // ---- epilogue ----
    const int gr0 = row0 + wm * 64 + (lane >> 2);
    const int gc0 = col0 + wn * 32 + (lane & 3) * 2;

    #pragma unroll
    for (int mt = 0; mt < 4; ++mt)
        #pragma unroll
        for (int nt = 0; nt < 4; ++nt) {
            const int gr = gr0 + mt * 16;
            const int gc = gc0 + nt * 8;
            const float* c = acc[mt][nt];
            if (MODE == 0) {
                if (z == 2) {            // V: fp16, transposed Vt[(b*1024+n)][t]
                    const int b = gr >> 11, t = gr & 2047;
                    const size_t o = ((size_t)(b * 1024 + gc)) * 2048 + t;
                    g_Vt[o]            = __float2half(c[0]);
                    g_Vt[o + 2048]     = __float2half(c[1]);
                    g_Vt[o + 8]        = __float2half(c[2]);
                    g_Vt[o + 2048 + 8] = __float2half(c[3]);
                } else {                 // Q or K: fp16 row-major
                    fp16* d = (z == 0) ? g_Q : g_K;
                    const size_t o = (size_t)gr * 1024 + gc;
                    *(__half2*)(d + o)            = __floats2half2_rn(c[0], c[1]);
                    *(__half2*)(d + o + 8 * 1024) = __floats2half2_rn(c[2], c[3]);
                }
            } else if (MODE == 1) {
                float* p = g_S + ((size_t)z << 22) + (size_t)gr * 2048 + gc;
                *(float2*)p              = make_float2(c[0] * 0.03125f, c[1] * 0.03125f);
                *(float2*)(p + 8 * 2048) = make_float2(c[2] * 0.03125f, c[3] * 0.03125f);
            } else {
                float* p = outp + ((size_t)z << 21) + (size_t)gr * 1024 + gc;
                *(float2*)p              = make_float2(c[0], c[1]);
                *(float2*)(p + 8 * 1024) = make_float2(c[2], c[3]);
            }
        }

    // ---- dependency arrive (Q/K projections feed fused QK tiles) ----
    if (MODE == 0 && z < 2) {
        __threadfence();
        __syncthreads();
        if (tid == 0) atomicAdd(&g_cnt[z * 64 + by], 1);
    }
}

// ---------------- mega kernel: QKV projections + QK gemm ----------------------
__global__ void __launch_bounds__(256)
mega_kernel()
{
    const int b = blockIdx.x;
    if (b < 1024) {                     // Q/K projections: z = b/512
        const int z = b >> 9, r = b & 511;
        gemm_body<0>(g_x, 1024, g_W + (size_t)z * 1024 * 1024, 1024,
                     1024, nullptr, r & 7, r >> 3, z);
    } else if (b < 1536) {              // V projection
        const int r = b - 1024;
        gemm_body<0>(g_x, 1024, g_W + (size_t)2 * 1024 * 1024, 1024,
                     1024, nullptr, r & 7, r >> 3, 2);
    } else {                            // QK tiles, spin on Q/K row blocks
        const int j = b - 1536;
        const int z = j >> 8, by = (j >> 4) & 15, bx = j & 15;
        const int qb = z * 16 + by;     // Q global 128-row block
        const int kb = 64 + z * 16 + bx;
        if (threadIdx.x == 0) {
            while (ld_acq(&g_cnt[qb]) < 8 || ld_acq(&g_cnt[kb]) < 8)
                __nanosleep(64);
        }
        __syncthreads();
        const size_t bo = (size_t)z << 21;   // z*2048*1024
        gemm_body<1>(g_Q + bo, 1024, g_K + bo, 1024, 1024, nullptr, bx, by, z);
    }
}

__global__ void __launch_bounds__(256)
pv_kernel(float* __restrict__ out)
{
    const size_t ao = (size_t)blockIdx.z << 22;   // b*2048*2048
    const size_t bo = (size_t)blockIdx.z << 21;   // b*1024*2048
    gemm_body<2>(g_P + ao, 2048, g_Vt + bo, 2048, 2048, out,
                 blockIdx.x, blockIdx.y, blockIdx.z);
}

// One launch converting x then Wq/Wk/Wv; block 0 also zeroes the dep counters.
#define N4_X (8192 * 1024 / 4)
#define N4_W (1024 * 1024 / 4)
__global__ void __launch_bounds__(256)
convert_all_kernel(const float* __restrict__ x, const float* __restrict__ Wq,
                   const float* __restrict__ Wk, const float* __restrict__ Wv)
{
    if (blockIdx.x == 0 && threadIdx.x < 128) g_cnt[threadIdx.x] = 0;

    const int i = blockIdx.x * blockDim.x + threadIdx.x;
    const float* src;
    fp16* dst;
    int k;
    if (i < N4_X) {
        src = x; dst = g_x; k = i;
    } else {
        int j = i - N4_X;
        int w = j / N4_W;
        k = j - w * N4_W;
        src = (w == 0) ? Wq : (w == 1) ? Wk : Wv;
        dst = g_W + (size_t)w * 1024 * 1024;
    }
    float4 v = *(const float4*)(src + (size_t)k * 4);
    __half2* d = (__half2*)(dst + (size_t)k * 4);
    d[0] = __floats2half2_rn(v.x, v.y);
    d[1] = __floats2half2_rn(v.z, v.w);
}

__global__ void __launch_bounds__(256)
softmax_kernel()
{
    size_t ro = (size_t)blockIdx.x * 2048;
    const float* p = g_S + ro;
    const int t = threadIdx.x;
    __shared__ float red[8];

    float v[8];
    float m = -1e30f;
    #pragma unroll
    for (int i = 0; i < 8; ++i) {
        v[i] = p[t + i * 256];
        m = fmaxf(m, v[i]);
    }
    #pragma unroll
    for (int o = 16; o; o >>= 1) m = fmaxf(m, __shfl_xor_sync(0xffffffffu, m, o));
    if ((t & 31) == 0) red[t >> 5] = m;
    __syncthreads();
    m = red[0];
    #pragma unroll
    for (int i = 1; i < 8; ++i) m = fmaxf(m, red[i]);
    __syncthreads();

    float s = 0.f;
    #pragma unroll
    for (int i = 0; i < 8; ++i) {
        v[i] = __expf(v[i] - m);
        s += v[i];
    }
    #pragma unroll
    for (int o = 16; o; o >>= 1) s += __shfl_xor_sync(0xffffffffu, s, o);
    if ((t & 31) == 0) red[t >> 5] = s;
    __syncthreads();
    s = red[0];
    #pragma unroll
    for (int i = 1; i < 8; ++i) s += red[i];

    const float inv = 1.0f / s;
    #pragma unroll
    for (int i = 0; i < 8; ++i) {
        size_t o = ro + t + i * 256;
        g_P[o] = __float2half(v[i] * inv);
    }
}

// ---------------- launch ------------------------------------------------------
extern "C" void kernel_launch(void* const* d_in, const int* in_sizes, int n_in,
                              void* d_out, int out_size)
{
    const float* x  = (const float*)d_in[0];
    const float* Wq = (const float*)d_in[1];
    const float* Wk = (const float*)d_in[2];
    const float* Wv = (const float*)d_in[3];
    float* out = (float*)d_out;

    cudaFuncSetAttribute(mega_kernel, cudaFuncAttributeMaxDynamicSharedMemorySize, SM_TOTAL);
    cudaFuncSetAttribute(pv_kernel,   cudaFuncAttributeMaxDynamicSharedMemorySize, SM_TOTAL);

    {
        int n4 = N4_X + 3 * N4_W;
        convert_all_kernel<<<(n4 + 255) / 256, 256>>>(x, Wq, Wk, Wv);
    }

    // QKproj(1024) + Vproj(512) + QK(1024) in one launch
    mega_kernel<<<2560, 256, SM_TOTAL>>>();

    softmax_kernel<<<4 * 2048, 256>>>();

    dim3 g3(8, 16, 4);    // PV: 2048x1024, K=2048
    pv_kernel<<<g3, 256, SM_TOTAL>>>(out);
}